// round 15
// baseline (speedup 1.0000x reference)
#include <cuda_runtime.h>

#define HH    8
#define DD    128
#define NEXP  4
#define MAXL  16384
#define MAXS  8
#define MAXB  32                      // max (sample,expert) buckets
#define NRB   64                      // routing blocks (= MAXL/PBT)
#define PBT   256                     // threads/block
#define PBW   (PBT / 32)              // warps per routing block

// ---- scratch (device globals; zero-initialized; no allocation allowed) ----
__device__ float4   g_pack [MAXL];          // {p0, p1, w0, w1} per token
__device__ int      g_agg  [NRB * MAXB];    // per-routing-block bucket aggregates
__device__ unsigned g_epoch;                // bumped by k0 each run (monotonic)
__device__ unsigned g_bar1;                 // routing internal barrier (monotonic)
__device__ unsigned g_bar2;                 // routing completion     (monotonic)

// ---------------------------------------------------------------------------
// k0: bump the epoch. Stream order guarantees every block of the fused
// kernel observes the new value -> free replay-safe run id.
// ---------------------------------------------------------------------------
__global__ void k0_epoch() { g_epoch = g_epoch + 1u; }

// ---------------------------------------------------------------------------
// Fused kernel. Blocks [0, NRB): routing + scan + packed destinations.
// Blocks [NRB, NRB+L): one-token scatter: prefetch -> spin on completion
// counter -> stores. Monotonic counters + epoch => no resets, no races.
// ---------------------------------------------------------------------------
__global__ void fused(
    const float* __restrict__ q, const float* __restrict__ k, const float* __restrict__ v,
    const float* __restrict__ gk, const float* __restrict__ beta,
    const float* __restrict__ e_in, const int* __restrict__ cu,
    int L, int S,
    float* __restrict__ o_q, float* __restrict__ o_k, float* __restrict__ o_v,
    float* __restrict__ o_gk, float* __restrict__ o_beta,
    float* __restrict__ o_e, float* __restrict__ o_mask,
    float* __restrict__ o_off, float* __restrict__ o_state,
    float* __restrict__ o_gs)
{
    const unsigned E = ((volatile unsigned*)&g_epoch)[0];   // stable during launch
    const int tid = threadIdx.x;

    if (blockIdx.x < NRB) {
        // ================= ROUTING PATH =================
        const int b    = blockIdx.x;
        const int lane = tid & 31;
        const int warp = tid >> 5;
        const int SN   = S * NEXP;
        const unsigned lt = (1u << lane) - 1u;

        __shared__ int wcnt[MAXB][PBW + 1];
        __shared__ int wexc[MAXB][PBW + 1];
        __shared__ int blkexc[MAXB];
        __shared__ int s_tot[MAXB];
        __shared__ int s_off[MAXB];

        int t = b * PBT + tid;
        bool act = (t < L);
        int bk0 = -1, bk1 = -1;
        float w0 = 0.0f, w1 = 0.0f;
        if (act) {
            float4 xv = *(const float4*)(e_in + (size_t)t * NEXP);
            float x[NEXP] = {xv.x, xv.y, xv.z, xv.w};
            float m = fmaxf(fmaxf(x[0], x[1]), fmaxf(x[2], x[3]));
            float ssum = 0.0f;
#pragma unroll
            for (int i = 0; i < NEXP; i++) { x[i] = expf(x[i] - m); ssum += x[i]; }
            float inv = 1.0f / ssum;
#pragma unroll
            for (int i = 0; i < NEXP; i++) x[i] *= inv;

            int b0 = 0; w0 = x[0];
#pragma unroll
            for (int i = 1; i < NEXP; i++) if (x[i] > w0) { w0 = x[i]; b0 = i; }
            int b1 = -1; w1 = -1e30f;
#pragma unroll
            for (int i = 0; i < NEXP; i++) if (i != b0 && x[i] > w1) { w1 = x[i]; b1 = i; }

            int s = 0;
            while (s + 1 < S && t >= cu[s + 1]) s++;

            __stcs((float4*)(o_e + (size_t)t * NEXP), make_float4(x[0], x[1], x[2], x[3]));
            float mk[NEXP];
#pragma unroll
            for (int i = 0; i < NEXP; i++) mk[i] = (i == b0 || i == b1) ? 1.0f : 0.0f;
            __stcs((float4*)(o_mask + (size_t)t * NEXP), make_float4(mk[0], mk[1], mk[2], mk[3]));

            bk0 = s * NEXP + b0;
            bk1 = s * NEXP + b1;
        }

        int r0loc = 0, r1loc = 0;
#pragma unroll
        for (int B = 0; B < MAXB; B++) {
            unsigned msk = __ballot_sync(0xffffffffu, bk0 == B || bk1 == B);
            if (lane == 0) wcnt[B][warp] = __popc(msk);
            if (B == bk0) r0loc = __popc(msk & lt);
            if (B == bk1) r1loc = __popc(msk & lt);
        }
        __syncthreads();

        if (tid < MAXB) {
            int B = tid, acc = 0;
#pragma unroll
            for (int w = 0; w < PBW; w++) { wexc[B][w] = acc; acc += wcnt[B][w]; }
            g_agg[b * MAXB + B] = acc;
        }

        // internal barrier over NRB routing blocks: monotonic counter vs 64*E
        __syncthreads();
        __threadfence();
        if (tid == 0) {
            atomicAdd(&g_bar1, 1u);
            while (((volatile unsigned*)&g_bar1)[0] < (unsigned)NRB * E) { __nanosleep(32); }
        }
        __syncthreads();
        __threadfence();

        // redundant prefix over aggregate table (warp 0; lane = bucket)
        if (warp == 0) {
            int excl = 0, tot = 0;
            for (int p = 0; p < NRB; p++) {
                int val = g_agg[p * MAXB + lane];
                if (p < b) excl += val;
                tot += val;
            }
            blkexc[lane] = excl;
            s_tot[lane]  = tot;
            int incl = tot;
#pragma unroll
            for (int off = 1; off < 32; off <<= 1) {
                int y = __shfl_up_sync(0xffffffffu, incl, off);
                if (lane >= off) incl += y;
            }
            s_off[lane] = incl - tot;        // bucket exclusive offsets
        }
        __syncthreads();

        if (act) {
            int p0 = s_off[bk0] + blkexc[bk0] + wexc[bk0][warp] + r0loc;
            int p1 = s_off[bk1] + blkexc[bk1] + wexc[bk1][warp] + r1loc;
            g_pack[t] = make_float4(__int_as_float(p0), __int_as_float(p1), w0, w1);
        }

        if (b == NRB - 1 && tid == 0) {
            int acc = 0;
            o_off[0] = 0.0f;
            for (int i = 0; i < SN; i++) {
                int c = s_tot[i];
                o_state[i] = (float)c;
                acc += c;
                o_off[i + 1] = (float)acc;
            }
        }

        // signal completion (release)
        __threadfence();
        __syncthreads();
        if (tid == 0) atomicAdd(&g_bar2, 1u);
    } else {
        // ================= SCATTER PATH (one token, straight-line) =========
        const int t = blockIdx.x - NRB;
        const int i = tid;
        const int ROW = HH * DD;             // 1024 floats = 256 float4

        const float4* qs = (const float4*)(q + (size_t)t * ROW);
        const float4* ks = (const float4*)(k + (size_t)t * ROW);
        const float4* vs = (const float4*)(v + (size_t)t * ROW);
        float4 a = __ldcs(qs + i);
        float4 bb = __ldcs(ks + i);
        float4 c = __ldcs(vs + i);
        float g = 0.0f, bt = 0.0f;
        if (i < HH) {
            g  = gk[(size_t)t * HH + i];
            bt = beta[(size_t)t * HH + i];
        }

        // wait for routing completion of THIS run (wave-1 only ever waits)
        if (tid == 0) {
            while (((volatile unsigned*)&g_bar2)[0] < (unsigned)NRB * E) { __nanosleep(64); }
            __threadfence();                 // acquire
        }
        __syncthreads();

        float4 pk = g_pack[t];
        long  p0 = __float_as_int(pk.x);
        long  p1 = __float_as_int(pk.y);
        float w0 = pk.z, w1 = pk.w;

        float4* qd0 = (float4*)(o_q + (size_t)p0 * ROW);
        float4* qd1 = (float4*)(o_q + (size_t)p1 * ROW);
        float4* kd0 = (float4*)(o_k + (size_t)p0 * ROW);
        float4* kd1 = (float4*)(o_k + (size_t)p1 * ROW);
        float4* vd0 = (float4*)(o_v + (size_t)p0 * ROW);
        float4* vd1 = (float4*)(o_v + (size_t)p1 * ROW);

        __stcs(qd0 + i, make_float4(a.x * w0, a.y * w0, a.z * w0, a.w * w0));
        __stcs(qd1 + i, make_float4(a.x * w1, a.y * w1, a.z * w1, a.w * w1));
        __stcs(kd0 + i, make_float4(bb.x * w0, bb.y * w0, bb.z * w0, bb.w * w0));
        __stcs(kd1 + i, make_float4(bb.x * w1, bb.y * w1, bb.z * w1, bb.w * w1));
        __stcs(vd0 + i, c);
        __stcs(vd1 + i, c);

        if (i < HH) {
            o_gk[(size_t)p0 * HH + i]   = g;
            o_gk[(size_t)p1 * HH + i]   = g;
            o_beta[(size_t)p0 * HH + i] = bt;
            o_beta[(size_t)p1 * HH + i] = bt;
        }
        if (i == 0) {
            o_gs[p0] = (float)t;
            o_gs[p1] = (float)t;
        }
    }
}

// ---------------------------------------------------------------------------
extern "C" void kernel_launch(void* const* d_in, const int* in_sizes, int n_in,
                              void* d_out, int out_size)
{
    const float* q    = (const float*)d_in[0];
    const float* k    = (const float*)d_in[1];
    const float* v    = (const float*)d_in[2];
    const float* gk   = (const float*)d_in[3];
    const float* beta = (const float*)d_in[4];
    const float* e    = (const float*)d_in[5];
    const int*   cu   = (const int*)d_in[6];

    int L = in_sizes[0] / (HH * DD);
    int S = in_sizes[6] - 1;

    float* out = (float*)d_out;
    size_t LKHD = (size_t)L * 2 * HH * DD;
    float* o_q     = out;
    float* o_k     = o_q + LKHD;
    float* o_v     = o_k + LKHD;
    float* o_gk    = o_v + LKHD;
    float* o_beta  = o_gk + (size_t)L * 2 * HH;
    float* o_e     = o_beta + (size_t)L * 2 * HH;
    float* o_mask  = o_e + (size_t)L * NEXP;
    float* o_off   = o_mask + (size_t)L * NEXP;
    float* o_state = o_off + (size_t)(S * NEXP + 1);
    float* o_gs    = o_state + (size_t)(S * NEXP);

    k0_epoch<<<1, 1>>>();
    fused<<<NRB + L, PBT>>>(q, k, v, gk, beta, e, cu, L, S,
                            o_q, o_k, o_v, o_gk, o_beta,
                            o_e, o_mask, o_off, o_state, o_gs);
}

// round 16
// speedup vs baseline: 1.0612x; 1.0612x over previous
#include <cuda_runtime.h>

#define HH    8
#define DD    128
#define NEXP  4
#define MAXL  16384
#define MAXS  8
#define MAXB  32                      // max (sample,expert) buckets
#define MAXPB 64                      // prologue blocks
#define PBT   256                     // prologue threads/block
#define PBW   (PBT / 32)              // warps per prologue block

// ---- scratch (device globals; zero-initialized; no allocation allowed) ----
__device__ int      g_sel_e [2 * MAXL];
__device__ float    g_sel_v [2 * MAXL];
__device__ int      g_rank  [2 * MAXL];     // global within-bucket rank
__device__ int      g_sample[MAXL];
__device__ int      g_offs  [MAXB + 1];
__device__ int      g_agg   [MAXPB * MAXB]; // per-block bucket aggregates
__device__ int      g_barcnt;               // barrier arrival counter (self-reset)
__device__ unsigned g_gen;                  // monotonic generation counter

// ---------------------------------------------------------------------------
// Prologue: routing + bucket ranks via ballots (runtime SN buckets, not the
// padded MAXB), ONE grid barrier over 64 co-resident blocks, redundant
// per-block prefix over the aggregate table. PDL-triggers on completion.
// ---------------------------------------------------------------------------
__global__ void __launch_bounds__(PBT) route_scan(
    const float* __restrict__ e_in, const int* __restrict__ cu,
    int L, int S,
    float* __restrict__ o_e, float* __restrict__ o_mask,
    float* __restrict__ o_off, float* __restrict__ o_state)
{
    const int b    = blockIdx.x;
    const int tid  = threadIdx.x;
    const int lane = tid & 31;
    const int warp = tid >> 5;               // PBW warps
    const int SN   = S * NEXP;               // 16 actual buckets
    const unsigned lt = (1u << lane) - 1u;

    __shared__ int wcnt[MAXB][PBW + 1];      // padded
    __shared__ int wexc[MAXB][PBW + 1];
    __shared__ int blkexc[MAXB];
    __shared__ int s_tot[MAXB];

    // ---- routing (one token per thread) ----
    int t = b * PBT + tid;
    bool act = (t < L);
    int bk0 = -1, bk1 = -1;
    if (act) {
        float4 xv = *(const float4*)(e_in + (size_t)t * NEXP);
        float x[NEXP] = {xv.x, xv.y, xv.z, xv.w};
        float m = fmaxf(fmaxf(x[0], x[1]), fmaxf(x[2], x[3]));
        float ssum = 0.0f;
#pragma unroll
        for (int i = 0; i < NEXP; i++) { x[i] = expf(x[i] - m); ssum += x[i]; }
        float inv = 1.0f / ssum;
#pragma unroll
        for (int i = 0; i < NEXP; i++) x[i] *= inv;

        int b0 = 0; float v0 = x[0];
#pragma unroll
        for (int i = 1; i < NEXP; i++) if (x[i] > v0) { v0 = x[i]; b0 = i; }
        int b1 = -1; float v1 = -1e30f;
#pragma unroll
        for (int i = 0; i < NEXP; i++) if (i != b0 && x[i] > v1) { v1 = x[i]; b1 = i; }

        int s = 0;
        while (s + 1 < S && t >= cu[s + 1]) s++;

        __stcs((float4*)(o_e + (size_t)t * NEXP), make_float4(x[0], x[1], x[2], x[3]));
        float mk[NEXP];
#pragma unroll
        for (int i = 0; i < NEXP; i++) mk[i] = (i == b0 || i == b1) ? 1.0f : 0.0f;
        __stcs((float4*)(o_mask + (size_t)t * NEXP), make_float4(mk[0], mk[1], mk[2], mk[3]));

        g_sel_e[2 * t]     = b0;  g_sel_v[2 * t]     = v0;
        g_sel_e[2 * t + 1] = b1;  g_sel_v[2 * t + 1] = v1;
        g_sample[t] = s;
        bk0 = s * NEXP + b0;
        bk1 = s * NEXP + b1;
    }

    // ---- per-warp ballots over the SN ACTUAL buckets (16, not 32) ----
    int r0loc = 0, r1loc = 0;
    for (int B = 0; B < SN; B++) {
        unsigned msk = __ballot_sync(0xffffffffu, bk0 == B || bk1 == B);
        if (lane == 0) wcnt[B][warp] = __popc(msk);
        if (B == bk0) r0loc = __popc(msk & lt);
        if (B == bk1) r1loc = __popc(msk & lt);
    }
    __syncthreads();

    // ---- per-block warp-exclusive offsets + block aggregates ----
    if (tid < SN) {
        int B = tid, acc = 0;
#pragma unroll
        for (int w = 0; w < PBW; w++) { wexc[B][w] = acc; acc += wcnt[B][w]; }
        g_agg[b * MAXB + B] = acc;
    }

    // ---- ONE grid barrier (64 co-resident blocks; replay-safe gen counter) --
    __syncthreads();
    __threadfence();
    if (tid == 0) {
        unsigned gen = ((volatile unsigned*)&g_gen)[0];
        int old = atomicAdd(&g_barcnt, 1);
        if (old == (int)gridDim.x - 1) {
            g_barcnt = 0;
            __threadfence();
            atomicAdd(&g_gen, 1);            // release
        } else {
            while (((volatile unsigned*)&g_gen)[0] == gen) { __nanosleep(32); }
        }
    }
    __syncthreads();
    __threadfence();

    // ---- redundant prefix over aggregate table (warp 0; lane = bucket) ----
    if (warp == 0 && lane < SN) {
        int excl = 0, tot = 0;
        for (int p = 0; p < (int)gridDim.x; p++) {
            int val = g_agg[p * MAXB + lane];
            if (p < b) excl += val;
            tot += val;
        }
        blkexc[lane] = excl;
        s_tot[lane]  = tot;
    }
    __syncthreads();

    // ---- absolute within-bucket ranks ----
    if (act) {
        g_rank[2 * t]     = blkexc[bk0] + wexc[bk0][warp] + r0loc;
        g_rank[2 * t + 1] = blkexc[bk1] + wexc[bk1][warp] + r1loc;
    }

    // ---- last block: offsets + state_sizes ----
    if (b == (int)gridDim.x - 1 && tid == 0) {
        int acc = 0;
        g_offs[0] = 0;
        o_off[0] = 0.0f;
        for (int i = 0; i < SN; i++) {
            int c = s_tot[i];
            o_state[i] = (float)c;
            acc += c;
            g_offs[i + 1] = acc;
            o_off[i + 1] = (float)acc;
        }
    }

    // ---- release PDL dependents as soon as writes are committed ----
    cudaTriggerProgrammaticLaunchCompletion();
}

// ---------------------------------------------------------------------------
// K4 with PDL — byte-identical to the proven 88.8us/78% R12 version:
// prefetch source rows (independent of routing), sync, scattered post-sync
// loads. NO __launch_bounds__ (ptxas must keep prefetch live in regs).
// ---------------------------------------------------------------------------
__global__ void k4_scatter(
    const float* __restrict__ q, const float* __restrict__ k, const float* __restrict__ v,
    const float* __restrict__ gk, const float* __restrict__ beta,
    float* __restrict__ o_q, float* __restrict__ o_k, float* __restrict__ o_v,
    float* __restrict__ o_gk, float* __restrict__ o_beta, float* __restrict__ o_gs)
{
    const int t = blockIdx.x;
    const int i = threadIdx.x;
    const int ROW = HH * DD;               // 1024 floats = 256 float4

    // ---- prefetch (independent of route_scan results) ----
    const float4* qs = (const float4*)(q + (size_t)t * ROW);
    const float4* ks = (const float4*)(k + (size_t)t * ROW);
    const float4* vs = (const float4*)(v + (size_t)t * ROW);
    float4 a = __ldcs(qs + i);
    float4 b = __ldcs(ks + i);
    float4 c = __ldcs(vs + i);
    float g = 0.0f, bt = 0.0f;
    if (i < HH) {
        g  = gk[(size_t)t * HH + i];
        bt = beta[(size_t)t * HH + i];
    }

    // ---- wait for route_scan's writes to be visible ----
    cudaGridDependencySynchronize();

    int s = g_sample[t];
    int e0 = g_sel_e[2 * t], e1 = g_sel_e[2 * t + 1];
    float w0 = g_sel_v[2 * t], w1 = g_sel_v[2 * t + 1];
    long p0 = (long)g_offs[s * NEXP + e0] + g_rank[2 * t];
    long p1 = (long)g_offs[s * NEXP + e1] + g_rank[2 * t + 1];

    float4* qd0 = (float4*)(o_q + (size_t)p0 * ROW);
    float4* qd1 = (float4*)(o_q + (size_t)p1 * ROW);
    float4* kd0 = (float4*)(o_k + (size_t)p0 * ROW);
    float4* kd1 = (float4*)(o_k + (size_t)p1 * ROW);
    float4* vd0 = (float4*)(o_v + (size_t)p0 * ROW);
    float4* vd1 = (float4*)(o_v + (size_t)p1 * ROW);

    __stcs(qd0 + i, make_float4(a.x * w0, a.y * w0, a.z * w0, a.w * w0));
    __stcs(qd1 + i, make_float4(a.x * w1, a.y * w1, a.z * w1, a.w * w1));
    __stcs(kd0 + i, make_float4(b.x * w0, b.y * w0, b.z * w0, b.w * w0));
    __stcs(kd1 + i, make_float4(b.x * w1, b.y * w1, b.z * w1, b.w * w1));
    __stcs(vd0 + i, c);
    __stcs(vd1 + i, c);

    if (i < HH) {
        o_gk[(size_t)p0 * HH + i]   = g;
        o_gk[(size_t)p1 * HH + i]   = g;
        o_beta[(size_t)p0 * HH + i] = bt;
        o_beta[(size_t)p1 * HH + i] = bt;
    }
    if (i == 0) {
        o_gs[p0] = (float)t;
        o_gs[p1] = (float)t;
    }
}

// ---------------------------------------------------------------------------
extern "C" void kernel_launch(void* const* d_in, const int* in_sizes, int n_in,
                              void* d_out, int out_size)
{
    const float* q    = (const float*)d_in[0];
    const float* k    = (const float*)d_in[1];
    const float* v    = (const float*)d_in[2];
    const float* gk   = (const float*)d_in[3];
    const float* beta = (const float*)d_in[4];
    const float* e    = (const float*)d_in[5];
    const int*   cu   = (const int*)d_in[6];

    int L = in_sizes[0] / (HH * DD);
    int S = in_sizes[6] - 1;

    float* out = (float*)d_out;
    size_t LKHD = (size_t)L * 2 * HH * DD;
    float* o_q     = out;
    float* o_k     = o_q + LKHD;
    float* o_v     = o_k + LKHD;
    float* o_gk    = o_v + LKHD;
    float* o_beta  = o_gk + (size_t)L * 2 * HH;
    float* o_e     = o_beta + (size_t)L * 2 * HH;
    float* o_mask  = o_e + (size_t)L * NEXP;
    float* o_off   = o_mask + (size_t)L * NEXP;
    float* o_state = o_off + (size_t)(S * NEXP + 1);
    float* o_gs    = o_state + (size_t)(S * NEXP);

    int nblk = (L + PBT - 1) / PBT;           // 64 for L=16384
    route_scan<<<nblk, PBT>>>(e, cu, L, S, o_e, o_mask, o_off, o_state);

    // k4 with Programmatic Dependent Launch: overlap its load phase with
    // route_scan's execution.
    cudaLaunchConfig_t cfg = {};
    cfg.gridDim  = dim3((unsigned)L, 1, 1);
    cfg.blockDim = dim3(256, 1, 1);
    cfg.dynamicSmemBytes = 0;
    cfg.stream = 0;
    cudaLaunchAttribute attrs[1];
    attrs[0].id = cudaLaunchAttributeProgrammaticStreamSerialization;
    attrs[0].val.programmaticStreamSerializationAllowed = 1;
    cfg.attrs = attrs;
    cfg.numAttrs = 1;
    cudaError_t err = cudaLaunchKernelEx(&cfg, k4_scatter,
                                         q, k, v, gk, beta,
                                         o_q, o_k, o_v, o_gk, o_beta, o_gs);
    if (err != cudaSuccess) {
        // Fallback: plain launch (still correct, just no overlap)
        k4_scatter<<<L, 256>>>(q, k, v, gk, beta, o_q, o_k, o_v, o_gk, o_beta, o_gs);
    }
}

// round 17
// speedup vs baseline: 1.0830x; 1.0205x over previous
#include <cuda_runtime.h>

#define HH    8
#define DD    128
#define NEXP  4
#define MAXL  16384
#define MAXS  8
#define MAXB  32                      // max (sample,expert) buckets (padded stride)
#define MAXPB 64                      // prologue blocks
#define PBT   256                     // prologue threads/block
#define PBW   (PBT / 32)              // warps per prologue block

// ---- scratch (device globals; zero-initialized; no allocation allowed) ----
__device__ int4     g_meta [MAXL];          // {pack0, pack1, w0bits, w1bits}; pack = (bk<<16)|lrank
__device__ int      g_agg  [MAXPB * MAXB];  // per-block bucket aggregates
__device__ int      g_base [MAXPB * MAXB];  // absolute base per (block, bucket)
__device__ unsigned g_fin;                  // monotonic arrival counter (never reset)

// ---------------------------------------------------------------------------
// Prologue: routing + per-block local ranks + aggregates. NO grid barrier:
// the last block to arrive (monotonic counter, replay-safe) alone builds the
// 64x16 base table + offsets/state_sizes. PDL-triggers dependents.
// ---------------------------------------------------------------------------
__global__ void __launch_bounds__(PBT) route_scan(
    const float* __restrict__ e_in, const int* __restrict__ cu,
    int L, int S,
    float* __restrict__ o_e, float* __restrict__ o_mask,
    float* __restrict__ o_off, float* __restrict__ o_state)
{
    const int b    = blockIdx.x;
    const int nblk = gridDim.x;              // 64
    const int tid  = threadIdx.x;
    const int lane = tid & 31;
    const int warp = tid >> 5;               // PBW warps
    const int SN   = S * NEXP;               // 16 actual buckets
    const unsigned lt = (1u << lane) - 1u;

    __shared__ int wcnt[MAXB][PBW + 1];
    __shared__ int wexc[MAXB][PBW + 1];
    __shared__ int s_finisher;
    // finisher-only tables
    __shared__ int s_base[MAXPB][MAXB];      // 8 KB
    __shared__ int s_off[MAXB];
    __shared__ int s_tot[MAXB];

    // ---- routing (one token per thread) ----
    int t = b * PBT + tid;
    bool act = (t < L);
    int bk0 = -1, bk1 = -1;
    float w0 = 0.0f, w1 = 0.0f;
    if (act) {
        float4 xv = *(const float4*)(e_in + (size_t)t * NEXP);
        float x[NEXP] = {xv.x, xv.y, xv.z, xv.w};
        float m = fmaxf(fmaxf(x[0], x[1]), fmaxf(x[2], x[3]));
        float ssum = 0.0f;
#pragma unroll
        for (int i = 0; i < NEXP; i++) { x[i] = expf(x[i] - m); ssum += x[i]; }
        float inv = 1.0f / ssum;
#pragma unroll
        for (int i = 0; i < NEXP; i++) x[i] *= inv;

        int b0 = 0; w0 = x[0];
#pragma unroll
        for (int i = 1; i < NEXP; i++) if (x[i] > w0) { w0 = x[i]; b0 = i; }
        int b1 = -1; w1 = -1e30f;
#pragma unroll
        for (int i = 0; i < NEXP; i++) if (i != b0 && x[i] > w1) { w1 = x[i]; b1 = i; }

        int s = 0;
        while (s + 1 < S && t >= cu[s + 1]) s++;

        __stcs((float4*)(o_e + (size_t)t * NEXP), make_float4(x[0], x[1], x[2], x[3]));
        float mk[NEXP];
#pragma unroll
        for (int i = 0; i < NEXP; i++) mk[i] = (i == b0 || i == b1) ? 1.0f : 0.0f;
        __stcs((float4*)(o_mask + (size_t)t * NEXP), make_float4(mk[0], mk[1], mk[2], mk[3]));

        bk0 = s * NEXP + b0;
        bk1 = s * NEXP + b1;
    }

    // ---- per-warp ballots over SN buckets ----
    int r0loc = 0, r1loc = 0;
    for (int B = 0; B < SN; B++) {
        unsigned msk = __ballot_sync(0xffffffffu, bk0 == B || bk1 == B);
        if (lane == 0) wcnt[B][warp] = __popc(msk);
        if (B == bk0) r0loc = __popc(msk & lt);
        if (B == bk1) r1loc = __popc(msk & lt);
    }
    __syncthreads();

    // ---- per-block warp-exclusive offsets + block aggregates ----
    if (tid < SN) {
        int B = tid, acc = 0;
#pragma unroll
        for (int w = 0; w < PBW; w++) { wexc[B][w] = acc; acc += wcnt[B][w]; }
        g_agg[b * MAXB + B] = acc;
    }
    __syncthreads();

    // ---- packed per-token meta: {bk<<16 | local_rank, ...}, weights ----
    if (act) {
        int lr0 = wexc[bk0][warp] + r0loc;
        int lr1 = wexc[bk1][warp] + r1loc;
        g_meta[t] = make_int4((bk0 << 16) | lr0, (bk1 << 16) | lr1,
                              __float_as_int(w0), __float_as_int(w1));
    }

    // ---- arrival; last block becomes the finisher (monotonic, no reset) ----
    __threadfence();                          // publish agg (+meta) before arrival
    __syncthreads();
    if (tid == 0) {
        unsigned old = atomicAdd(&g_fin, 1u);
        s_finisher = ((old % (unsigned)nblk) == (unsigned)(nblk - 1)) ? 1 : 0;
    }
    __syncthreads();
    if (!s_finisher) {
        cudaTriggerProgrammaticLaunchCompletion();
        return;
    }

    // ================= FINISHER (one block) =================
    __threadfence();                          // acquire all blocks' aggregates

    // cross-block exclusive scan per bucket: warp w handles buckets w, w+PBW, ...
    for (int B = warp; B < SN; B += PBW) {
        int carry = 0;
        for (int base = 0; base < nblk; base += 32) {
            int p = base + lane;
            int val = (p < nblk) ? g_agg[p * MAXB + B] : 0;
            int incl = val;
#pragma unroll
            for (int off = 1; off < 32; off <<= 1) {
                int y = __shfl_up_sync(0xffffffffu, incl, off);
                if (lane >= off) incl += y;
            }
            if (p < nblk) s_base[p][B] = carry + incl - val;
            carry += __shfl_sync(0xffffffffu, incl, 31);
        }
        if (lane == 0) s_tot[B] = carry;
    }
    __syncthreads();

    // bucket exclusive offsets (warp 0)
    if (warp == 0 && lane < 32) {
        int tot = (lane < SN) ? s_tot[lane] : 0;
        int incl = tot;
#pragma unroll
        for (int off = 1; off < 32; off <<= 1) {
            int y = __shfl_up_sync(0xffffffffu, incl, off);
            if (lane >= off) incl += y;
        }
        if (lane < SN) s_off[lane] = incl - tot;
    }
    __syncthreads();

    // absolute base table + outputs
    for (int idx = tid; idx < nblk * SN; idx += PBT) {
        int p = idx / SN, B = idx % SN;
        g_base[p * MAXB + B] = s_off[B] + s_base[p][B];
    }
    if (tid == 0) {
        int acc = 0;
        o_off[0] = 0.0f;
        for (int i = 0; i < SN; i++) {
            int c = s_tot[i];
            o_state[i] = (float)c;
            acc += c;
            o_off[i + 1] = (float)acc;
        }
    }
    cudaTriggerProgrammaticLaunchCompletion();
}

// ---------------------------------------------------------------------------
// K4 with PDL — proven R12 prefetch pattern (NO __launch_bounds__; prefetch
// must stay in regs across the sync). Post-sync: ONE int4 meta load + two
// L2-hot g_base lookups.
// ---------------------------------------------------------------------------
__global__ void k4_scatter(
    const float* __restrict__ q, const float* __restrict__ k, const float* __restrict__ v,
    const float* __restrict__ gk, const float* __restrict__ beta,
    float* __restrict__ o_q, float* __restrict__ o_k, float* __restrict__ o_v,
    float* __restrict__ o_gk, float* __restrict__ o_beta, float* __restrict__ o_gs)
{
    const int t = blockIdx.x;
    const int i = threadIdx.x;
    const int ROW = HH * DD;               // 1024 floats = 256 float4

    // ---- prefetch (independent of route_scan results) ----
    const float4* qs = (const float4*)(q + (size_t)t * ROW);
    const float4* ks = (const float4*)(k + (size_t)t * ROW);
    const float4* vs = (const float4*)(v + (size_t)t * ROW);
    float4 a = __ldcs(qs + i);
    float4 b = __ldcs(ks + i);
    float4 c = __ldcs(vs + i);
    float g = 0.0f, bt = 0.0f;
    if (i < HH) {
        g  = gk[(size_t)t * HH + i];
        bt = beta[(size_t)t * HH + i];
    }

    // ---- wait for route_scan's writes to be visible ----
    cudaGridDependencySynchronize();

    int4 mt = g_meta[t];
    int bk0 = mt.x >> 16, lr0 = mt.x & 0xFFFF;
    int bk1 = mt.y >> 16, lr1 = mt.y & 0xFFFF;
    float w0 = __int_as_float(mt.z), w1 = __int_as_float(mt.w);
    int rb = t >> 8;                        // token's routing block (PBT = 256)
    long p0 = (long)g_base[rb * MAXB + bk0] + lr0;
    long p1 = (long)g_base[rb * MAXB + bk1] + lr1;

    float4* qd0 = (float4*)(o_q + (size_t)p0 * ROW);
    float4* qd1 = (float4*)(o_q + (size_t)p1 * ROW);
    float4* kd0 = (float4*)(o_k + (size_t)p0 * ROW);
    float4* kd1 = (float4*)(o_k + (size_t)p1 * ROW);
    float4* vd0 = (float4*)(o_v + (size_t)p0 * ROW);
    float4* vd1 = (float4*)(o_v + (size_t)p1 * ROW);

    __stcs(qd0 + i, make_float4(a.x * w0, a.y * w0, a.z * w0, a.w * w0));
    __stcs(qd1 + i, make_float4(a.x * w1, a.y * w1, a.z * w1, a.w * w1));
    __stcs(kd0 + i, make_float4(b.x * w0, b.y * w0, b.z * w0, b.w * w0));
    __stcs(kd1 + i, make_float4(b.x * w1, b.y * w1, b.z * w1, b.w * w1));
    __stcs(vd0 + i, c);
    __stcs(vd1 + i, c);

    if (i < HH) {
        o_gk[(size_t)p0 * HH + i]   = g;
        o_gk[(size_t)p1 * HH + i]   = g;
        o_beta[(size_t)p0 * HH + i] = bt;
        o_beta[(size_t)p1 * HH + i] = bt;
    }
    if (i == 0) {
        o_gs[p0] = (float)t;
        o_gs[p1] = (float)t;
    }
}

// ---------------------------------------------------------------------------
extern "C" void kernel_launch(void* const* d_in, const int* in_sizes, int n_in,
                              void* d_out, int out_size)
{
    const float* q    = (const float*)d_in[0];
    const float* k    = (const float*)d_in[1];
    const float* v    = (const float*)d_in[2];
    const float* gk   = (const float*)d_in[3];
    const float* beta = (const float*)d_in[4];
    const float* e    = (const float*)d_in[5];
    const int*   cu   = (const int*)d_in[6];

    int L = in_sizes[0] / (HH * DD);
    int S = in_sizes[6] - 1;

    float* out = (float*)d_out;
    size_t LKHD = (size_t)L * 2 * HH * DD;
    float* o_q     = out;
    float* o_k     = o_q + LKHD;
    float* o_v     = o_k + LKHD;
    float* o_gk    = o_v + LKHD;
    float* o_beta  = o_gk + (size_t)L * 2 * HH;
    float* o_e     = o_beta + (size_t)L * 2 * HH;
    float* o_mask  = o_e + (size_t)L * NEXP;
    float* o_off   = o_mask + (size_t)L * NEXP;
    float* o_state = o_off + (size_t)(S * NEXP + 1);
    float* o_gs    = o_state + (size_t)(S * NEXP);

    int nblk = (L + PBT - 1) / PBT;           // 64 for L=16384
    route_scan<<<nblk, PBT>>>(e, cu, L, S, o_e, o_mask, o_off, o_state);

    // k4 with Programmatic Dependent Launch: overlap its load phase with
    // route_scan's execution.
    cudaLaunchConfig_t cfg = {};
    cfg.gridDim  = dim3((unsigned)L, 1, 1);
    cfg.blockDim = dim3(256, 1, 1);
    cfg.dynamicSmemBytes = 0;
    cfg.stream = 0;
    cudaLaunchAttribute attrs[1];
    attrs[0].id = cudaLaunchAttributeProgrammaticStreamSerialization;
    attrs[0].val.programmaticStreamSerializationAllowed = 1;
    cfg.attrs = attrs;
    cfg.numAttrs = 1;
    cudaError_t err = cudaLaunchKernelEx(&cfg, k4_scatter,
                                         q, k, v, gk, beta,
                                         o_q, o_k, o_v, o_gk, o_beta, o_gs);
    if (err != cudaSuccess) {
        // Fallback: plain launch (still correct, just no overlap)
        k4_scatter<<<L, 256>>>(q, k, v, gk, beta, o_q, o_k, o_v, o_gk, o_beta, o_gs);
    }
}